// round 2
// baseline (speedup 1.0000x reference)
#include <cuda_runtime.h>
#include <cuda_bf16.h>
#include <math.h>

// ---------------- problem constants ----------------
#define BATCH   32
#define DMODEL  4096
#define NH      32
#define NKV     8
#define GQA     4          // NH / NKV
#define HD      128
#define PBLOCK  64         // paged block size
#define NBLK    64         // blocks per sequence
#define LMAX    (NBLK * PBLOCK)   // 4096
#define QKVCOLS ((NH + 2 * NKV) * HD)  // 6144

// attention tiling
#define ASPLIT  512        // keys per split
#define NS      (LMAX / ASPLIT)   // 8 splits
#define TK      32         // keys per smem tile
#define KSTR    130        // smem K row stride (floats)

// split-K GEMM
#define KSPLITS 32
#define KRANGE  (DMODEL / KSPLITS)   // 128

// ---------------- device scratch (no runtime alloc allowed) ----------------
__device__ float g_qkv_part[KSPLITS * BATCH * QKVCOLS];   // ~25 MB
__device__ float g_qkv[BATCH * QKVCOLS];                  // rope'd q|k|v
__device__ float g_part[BATCH * NKV * NS * (GQA * 130)];  // per-split partials
__device__ float g_attn[BATCH * NH * HD];                 // attention output
__device__ float g_out_part[KSPLITS * BATCH * DMODEL];    // ~17 MB

// ---------------- f32x2 helpers ----------------
__device__ __forceinline__ unsigned long long pk2(float x, float y) {
    unsigned long long r;
    asm("mov.b64 %0, {%1, %2};" : "=l"(r) : "f"(x), "f"(y));
    return r;
}
__device__ __forceinline__ void upk2(unsigned long long v, float& x, float& y) {
    asm("mov.b64 {%0, %1}, %2;" : "=f"(x), "=f"(y) : "l"(v));
}
__device__ __forceinline__ void ffma2(unsigned long long& d,
                                      unsigned long long a,
                                      unsigned long long b) {
    asm("fma.rn.f32x2 %0, %1, %2, %0;" : "+l"(d) : "l"(a), "l"(b));
}

// ---------------- split-K GEMM ----------------
// MODE 0: C=g_qkv_part, A=Ain (hidden).  MODE 1: C=g_out_part, A=g_attn.
// block: 128 threads, 4 consecutive cols each; all 32 batch rows.
// grid: (N/512, KSPLITS)
template <int N, int MODE>
__global__ __launch_bounds__(128) void gemm_splitk(
    const float* __restrict__ Ain, const float* __restrict__ W)
{
    const float* __restrict__ A = (MODE == 0) ? Ain : (const float*)g_attn;
    float* __restrict__ Cpart   = (MODE == 0) ? g_qkv_part : g_out_part;

    __shared__ __align__(16) float a_s[KRANGE][34];   // pad: 8B-aligned pairs

    const int t  = threadIdx.x;
    const int k0 = blockIdx.y * KRANGE;
    const int c0 = blockIdx.x * 512 + t * 4;

    // load A tile [128 k][32 b], transposed so batch pairs are contiguous
    #pragma unroll 8
    for (int bb = 0; bb < 32; bb++)
        a_s[t][bb] = A[bb * DMODEL + k0 + t];
    __syncthreads();

    unsigned long long acc2[16][4];
    #pragma unroll
    for (int p = 0; p < 16; p++)
        #pragma unroll
        for (int j = 0; j < 4; j++)
            acc2[p][j] = 0ULL;

    const float* Wp = W + (size_t)k0 * N + c0;

    #pragma unroll 4
    for (int kk = 0; kk < KRANGE; kk++) {
        const float4 w4 = *(const float4*)(Wp + (size_t)kk * N);
        const unsigned long long wx = pk2(w4.x, w4.x);
        const unsigned long long wy = pk2(w4.y, w4.y);
        const unsigned long long wz = pk2(w4.z, w4.z);
        const unsigned long long ww = pk2(w4.w, w4.w);
        const unsigned long long* ap = (const unsigned long long*)(&a_s[kk][0]);
        #pragma unroll
        for (int p = 0; p < 16; p++) {
            const unsigned long long h2 = ap[p];
            ffma2(acc2[p][0], h2, wx);
            ffma2(acc2[p][1], h2, wy);
            ffma2(acc2[p][2], h2, wz);
            ffma2(acc2[p][3], h2, ww);
        }
    }

    float* Cb = Cpart + (size_t)blockIdx.y * 32 * N + c0;
    #pragma unroll
    for (int p = 0; p < 16; p++) {
        float4 r0, r1;
        upk2(acc2[p][0], r0.x, r1.x);
        upk2(acc2[p][1], r0.y, r1.y);
        upk2(acc2[p][2], r0.z, r1.z);
        upk2(acc2[p][3], r0.w, r1.w);
        *(float4*)(Cb + (size_t)(2 * p) * N)     = r0;
        *(float4*)(Cb + (size_t)(2 * p + 1) * N) = r1;
    }
}

// ---------------- reduce qkv partials + RoPE (into g_qkv) ----------------
__global__ __launch_bounds__(256) void rope_reduce_kernel(
    const int* __restrict__ position_ids)
{
    __shared__ float buf[QKVCOLS];
    __shared__ float cosv[64], sinv[64];
    const int b = blockIdx.x;
    const int t = threadIdx.x;

    for (int c = t; c < QKVCOLS; c += 256) {
        float v = 0.f;
        #pragma unroll
        for (int s = 0; s < KSPLITS; s++)
            v += g_qkv_part[(size_t)s * BATCH * QKVCOLS + b * QKVCOLS + c];
        buf[c] = v;
    }
    if (t < 64) {
        const double inv = exp(-(2.0 * t / 128.0) * log(1.0e6));
        const double ang = (double)position_ids[b] * inv;
        cosv[t] = (float)cos(ang);
        sinv[t] = (float)sin(ang);
    }
    __syncthreads();

    float* out = g_qkv + b * QKVCOLS;
    // rope heads 0..39 (32 q heads + 8 k heads, contiguous cols)
    for (int idx = t; idx < 40 * 64; idx += 256) {
        const int head = idx >> 6, i = idx & 63;
        const int base = head * 128;
        const float x1 = buf[base + i], x2 = buf[base + i + 64];
        const float c = cosv[i], s = sinv[i];
        out[base + i]      = x1 * c - x2 * s;
        out[base + i + 64] = x2 * c + x1 * s;
    }
    // v passthrough
    for (int c = 5120 + t; c < QKVCOLS; c += 256)
        out[c] = buf[c];
}

// ---------------- flash-decoding split attention ----------------
// grid (NS, NKV, BATCH), 128 threads. warp = GQA group; lane = key (scores) / dim (V).
__global__ __launch_bounds__(128) void attn_split_kernel(
    const float* __restrict__ k_cache, const float* __restrict__ v_cache,
    const int* __restrict__ block_offsets, const int* __restrict__ kv_seqlens)
{
    __shared__ __align__(16) float q_s[GQA * HD];
    __shared__ __align__(16) float k_s[TK * KSTR];
    __shared__ float p_s[GQA * TK];

    const int s    = blockIdx.x;
    const int kh   = blockIdx.y;
    const int b    = blockIdx.z;
    const int t    = threadIdx.x;
    const int g    = t >> 5;
    const int lane = t & 31;

    const int kv_len = kv_seqlens[b];
    const int last   = kv_len - 1;
    const int base0  = s * ASPLIT;

    float* P = g_part + (((size_t)(b * NKV + kh)) * NS + s) * (GQA * 130) + g * 130;

    if (base0 >= kv_len) {   // inactive split: neutral partial
        P[lane] = 0.f; P[lane + 32] = 0.f; P[lane + 64] = 0.f; P[lane + 96] = 0.f;
        if (lane == 0) { P[128] = -1e30f; P[129] = 0.f; }
        return;
    }

    // load q for this (b, kh) group
    #pragma unroll
    for (int i = 0; i < GQA; i++)
        q_s[i * HD + t] = g_qkv[b * QKVCOLS + (kh * GQA + i) * HD + t];

    const float* knew = g_qkv + b * QKVCOLS + NH * HD + kh * HD;
    const float* vnew = g_qkv + b * QKVCOLS + (NH + NKV) * HD + kh * HD;
    const int* btab = block_offsets + b * NBLK;
    const float scale = 0.08838834764831845f;  // 1/sqrt(128)

    float m = -1e30f, l = 0.f;
    float acc0 = 0.f, acc1 = 0.f, acc2v = 0.f, acc3 = 0.f;

    for (int tile = 0; tile < ASPLIT / TK; tile++) {
        const int base = base0 + tile * TK;       // multiple of 32 -> stays inside one page
        const int phys = btab[base >> 6];
        const size_t rowbase = ((size_t)(phys * PBLOCK + (base & 63)) * NKV + kh) * HD;
        const float* kb = k_cache + rowbase;

        // stage K tile (32 rows x 128), substituting the new token's row in-flight
        #pragma unroll
        for (int i = 0; i < 8; i++) {
            const int idx = i * 128 + t;
            const int r = idx >> 5, c4 = idx & 31;
            const float4 v4 = (base + r == last)
                ? *(const float4*)(knew + c4 * 4)
                : *(const float4*)(kb + (size_t)r * (NKV * HD) + c4 * 4);
            float* dst = k_s + r * KSTR + c4 * 4;
            dst[0] = v4.x; dst[1] = v4.y; dst[2] = v4.z; dst[3] = v4.w;
        }
        __syncthreads();

        // scores: thread (g, lane=key), f32x2 dot over HD
        unsigned long long d2 = 0ULL;
        const unsigned long long* kp = (const unsigned long long*)(k_s + lane * KSTR);
        const unsigned long long* qp = (const unsigned long long*)(q_s + (g << 7));
        #pragma unroll
        for (int jj = 0; jj < 64; jj++)
            ffma2(d2, kp[jj], qp[jj]);
        float lo, hi;
        upk2(d2, lo, hi);
        float sc = (lo + hi) * scale;
        if (base + lane >= kv_len) sc = -1e30f;

        // warp online softmax (per GQA group)
        float mt = sc;
        #pragma unroll
        for (int o = 16; o; o >>= 1)
            mt = fmaxf(mt, __shfl_xor_sync(0xffffffffu, mt, o));
        const float mnew = fmaxf(m, mt);
        const float corr = __expf(m - mnew);
        const float p = __expf(sc - mnew);
        float psum = p;
        #pragma unroll
        for (int o = 16; o; o >>= 1)
            psum += __shfl_xor_sync(0xffffffffu, psum, o);
        l = l * corr + psum;
        m = mnew;
        acc0 *= corr; acc1 *= corr; acc2v *= corr; acc3 *= corr;
        p_s[g * TK + lane] = p;
        __syncwarp();

        // V accumulate: V streamed straight from GMEM (coalesced 512B rows, read once)
        const float* vb = v_cache + rowbase;
        #pragma unroll
        for (int key = 0; key < TK; key++) {
            const float pk = p_s[g * TK + key];
            if (pk != 0.f) {
                const float* vr = (base + key == last)
                    ? vnew : (vb + (size_t)key * (NKV * HD));
                acc0 += pk * vr[lane];
                acc1 += pk * vr[lane + 32];
                acc2v += pk * vr[lane + 64];
                acc3 += pk * vr[lane + 96];
            }
        }
        __syncthreads();   // protect k_s before next tile's staging
    }

    P[lane]      = acc0;
    P[lane + 32] = acc1;
    P[lane + 64] = acc2v;
    P[lane + 96] = acc3;
    if (lane == 0) { P[128] = m; P[129] = l; }
}

// ---------------- combine splits ----------------
__global__ __launch_bounds__(128) void combine_kernel()
{
    const int kh = blockIdx.x, b = blockIdx.y, d = threadIdx.x;
    const float* P = g_part + ((size_t)(b * NKV + kh)) * NS * (GQA * 130);
    #pragma unroll
    for (int g = 0; g < GQA; g++) {
        float M = -1e30f;
        #pragma unroll
        for (int s = 0; s < NS; s++)
            M = fmaxf(M, P[s * (GQA * 130) + g * 130 + 128]);
        float Ls = 0.f, o = 0.f;
        #pragma unroll
        for (int s = 0; s < NS; s++) {
            const float* Ps = P + s * (GQA * 130) + g * 130;
            const float w = __expf(Ps[128] - M);
            Ls += w * Ps[129];
            o  += w * Ps[d];
        }
        g_attn[b * DMODEL + (kh * GQA + g) * HD + d] = o / Ls;
    }
}

// ---------------- reduce output split-K partials into d_out ----------------
__global__ __launch_bounds__(256) void reduce_out_kernel(float* __restrict__ out)
{
    const int i = blockIdx.x * 256 + threadIdx.x;
    if (i < BATCH * DMODEL) {
        float v = 0.f;
        #pragma unroll
        for (int s = 0; s < KSPLITS; s++)
            v += g_out_part[(size_t)s * BATCH * DMODEL + i];
        out[i] = v;
    }
}

// ---------------- launcher: kernel launches ONLY (graph-capture safe) ----------------
extern "C" void kernel_launch(void* const* d_in, const int* in_sizes, int n_in,
                              void* d_out, int out_size)
{
    const float* hidden  = (const float*)d_in[0];
    const float* wqkv    = (const float*)d_in[1];
    const float* wo      = (const float*)d_in[2];
    const float* k_cache = (const float*)d_in[3];
    const float* v_cache = (const float*)d_in[4];
    const int* pos_ids   = (const int*)d_in[5];
    const int* blk_off   = (const int*)d_in[6];
    const int* kv_lens   = (const int*)d_in[7];
    float* out = (float*)d_out;

    // 1) QKV projection (split-K partials into g_qkv_part)
    gemm_splitk<QKVCOLS, 0><<<dim3(QKVCOLS / 512, KSPLITS), 128>>>(hidden, wqkv);
    // 2) reduce partials + RoPE
    rope_reduce_kernel<<<BATCH, 256>>>(pos_ids);
    // 3) flash-decoding paged attention
    attn_split_kernel<<<dim3(NS, NKV, BATCH), 128>>>(k_cache, v_cache, blk_off, kv_lens);
    // 4) combine splits
    combine_kernel<<<dim3(NKV, BATCH), 128>>>();
    // 5) output projection (split-K partials into g_out_part, A = g_attn)
    gemm_splitk<DMODEL, 1><<<dim3(DMODEL / 512, KSPLITS), 128>>>(hidden, wo);
    // 6) final reduce into d_out
    reduce_out_kernel<<<(BATCH * DMODEL + 255) / 256, 256>>>(out);
}

// round 4
// speedup vs baseline: 1.3302x; 1.3302x over previous
#include <cuda_runtime.h>
#include <cuda_bf16.h>
#include <math.h>

// ---------------- problem constants ----------------
#define BATCH   32
#define DMODEL  4096
#define NH      32
#define NKV     8
#define GQA     4
#define HD      128
#define PBLOCK  64
#define NBLK    64
#define LMAX    (NBLK * PBLOCK)          // 4096
#define QKVCOLS ((NH + 2 * NKV) * HD)    // 6144

// attention tiling
#define ASPLIT  512
#define NS      (LMAX / ASPLIT)          // 8
#define TK      32
#define NT      (ASPLIT / TK)            // 16 tiles per split
#define KS      130                      // K smem stride (floats): 65 ULL, odd -> conflict-free LDS.64
#define VS      132                      // V smem stride (floats): 16B multiple -> conflict-free LDS.128
#define GSTR    132                      // partial: 128 dims + m + l, 16B-aligned group stride
#define SSTR    (GQA * GSTR)             // 528

// split-K GEMM
#define KSPLITS 32
#define KRANGE  (DMODEL / KSPLITS)       // 128

// ---------------- device scratch ----------------
__device__ float g_qkv_part[KSPLITS * BATCH * QKVCOLS];
__device__ __align__(16) float g_qkv[BATCH * QKVCOLS];
__device__ __align__(16) float g_part[BATCH * NKV * NS * SSTR];
__device__ __align__(16) float g_attn[BATCH * NH * HD];
__device__ float g_out_part[KSPLITS * BATCH * DMODEL];

// ---------------- f32x2 helpers ----------------
__device__ __forceinline__ unsigned long long pk2(float x, float y) {
    unsigned long long r;
    asm("mov.b64 %0, {%1, %2};" : "=l"(r) : "f"(x), "f"(y));
    return r;
}
__device__ __forceinline__ void upk2(unsigned long long v, float& x, float& y) {
    asm("mov.b64 {%0, %1}, %2;" : "=f"(x), "=f"(y) : "l"(v));
}
__device__ __forceinline__ void ffma2(unsigned long long& d,
                                      unsigned long long a,
                                      unsigned long long b) {
    asm("fma.rn.f32x2 %0, %1, %2, %0;" : "+l"(d) : "l"(a), "l"(b));
}

// ---------------- split-K GEMM ----------------
// MODE 0: C=g_qkv_part, A=Ain (hidden).  MODE 1: C=g_out_part, A=g_attn.
template <int N, int MODE>
__global__ __launch_bounds__(128) void gemm_splitk(
    const float* __restrict__ Ain, const float* __restrict__ W)
{
    const float* __restrict__ A = (MODE == 0) ? Ain : (const float*)g_attn;
    float* __restrict__ Cpart   = (MODE == 0) ? g_qkv_part : g_out_part;

    __shared__ __align__(16) float a_s[KRANGE][34];

    const int t  = threadIdx.x;
    const int k0 = blockIdx.y * KRANGE;
    const int c0 = blockIdx.x * 512 + t * 4;

    #pragma unroll 8
    for (int bb = 0; bb < 32; bb++)
        a_s[t][bb] = A[bb * DMODEL + k0 + t];
    __syncthreads();

    unsigned long long acc2[16][4];
    #pragma unroll
    for (int p = 0; p < 16; p++)
        #pragma unroll
        for (int j = 0; j < 4; j++)
            acc2[p][j] = 0ULL;

    const float* Wp = W + (size_t)k0 * N + c0;

    #pragma unroll 4
    for (int kk = 0; kk < KRANGE; kk++) {
        const float4 w4 = *(const float4*)(Wp + (size_t)kk * N);
        const unsigned long long wx = pk2(w4.x, w4.x);
        const unsigned long long wy = pk2(w4.y, w4.y);
        const unsigned long long wz = pk2(w4.z, w4.z);
        const unsigned long long ww = pk2(w4.w, w4.w);
        const unsigned long long* ap = (const unsigned long long*)(&a_s[kk][0]);
        #pragma unroll
        for (int p = 0; p < 16; p++) {
            const unsigned long long h2 = ap[p];
            ffma2(acc2[p][0], h2, wx);
            ffma2(acc2[p][1], h2, wy);
            ffma2(acc2[p][2], h2, wz);
            ffma2(acc2[p][3], h2, ww);
        }
    }

    float* Cb = Cpart + (size_t)blockIdx.y * 32 * N + c0;
    #pragma unroll
    for (int p = 0; p < 16; p++) {
        float4 r0, r1;
        upk2(acc2[p][0], r0.x, r1.x);
        upk2(acc2[p][1], r0.y, r1.y);
        upk2(acc2[p][2], r0.z, r1.z);
        upk2(acc2[p][3], r0.w, r1.w);
        *(float4*)(Cb + (size_t)(2 * p) * N)     = r0;
        *(float4*)(Cb + (size_t)(2 * p + 1) * N) = r1;
    }
}

// ---------------- reduce qkv partials + RoPE ----------------
// grid (6, BATCH): each block handles 1024 columns of one batch row.
__global__ __launch_bounds__(256) void rope_reduce_kernel(
    const int* __restrict__ position_ids)
{
    __shared__ float buf[1024];
    __shared__ float cosv[64], sinv[64];
    const int chunk = blockIdx.x;
    const int b = blockIdx.y;
    const int t = threadIdx.x;
    const int c0 = chunk * 1024;

    #pragma unroll
    for (int c = t; c < 1024; c += 256) {
        float v = 0.f;
        #pragma unroll
        for (int s = 0; s < KSPLITS; s++)
            v += g_qkv_part[(size_t)s * BATCH * QKVCOLS + b * QKVCOLS + c0 + c];
        buf[c] = v;
    }
    if (t < 64) {
        const double inv = exp(-(2.0 * t / 128.0) * log(1.0e6));
        const double ang = (double)position_ids[b] * inv;
        cosv[t] = (float)cos(ang);
        sinv[t] = (float)sin(ang);
    }
    __syncthreads();

    float* out = g_qkv + b * QKVCOLS + c0;
    if (c0 < 5120) {      // q heads + k heads: rope (8 heads per chunk)
        #pragma unroll
        for (int idx = t; idx < 512; idx += 256) {
            const int head = idx >> 6, i = idx & 63;
            const int lb = head * 128;
            const float x1 = buf[lb + i], x2 = buf[lb + i + 64];
            const float c = cosv[i], s = sinv[i];
            out[lb + i]      = x1 * c - x2 * s;
            out[lb + i + 64] = x2 * c + x1 * s;
        }
    } else {              // v passthrough
        #pragma unroll
        for (int c = t; c < 1024; c += 256)
            out[c] = buf[c];
    }
}

// ---------------- flash-decoding split attention (deferred softmax) ----------------
// grid (NS, NKV, BATCH), 128 threads; warp = GQA group.
__global__ __launch_bounds__(128) void attn_split_kernel(
    const float* __restrict__ k_cache, const float* __restrict__ v_cache,
    const int* __restrict__ block_offsets, const int* __restrict__ kv_seqlens)
{
    __shared__ __align__(16) float q_s[GQA * HD];          // 2 KB
    __shared__ __align__(16) float kv_s[2][TK * VS];       // 2 x 16.5 KB (K uses stride 130 inside)
    __shared__ float p_s[GQA * ASPLIT];                    // 8 KB

    const int s    = blockIdx.x;
    const int kh   = blockIdx.y;
    const int b    = blockIdx.z;
    const int t    = threadIdx.x;
    const int g    = t >> 5;
    const int lane = t & 31;

    const int kv_len = kv_seqlens[b];
    const int last   = kv_len - 1;
    const int base0  = s * ASPLIT;

    float* P = g_part + (((size_t)(b * NKV + kh)) * NS + s) * SSTR + g * GSTR;

    if (base0 >= kv_len) {
        const float4 z = {0.f, 0.f, 0.f, 0.f};
        *(float4*)(P + (lane << 2)) = z;
        if (lane == 0) { P[128] = -1e30f; P[129] = 0.f; }
        return;
    }

    #pragma unroll
    for (int i = 0; i < GQA; i++)
        q_s[i * HD + t] = g_qkv[b * QKVCOLS + (kh * GQA + i) * HD + t];

    const float* knew = g_qkv + b * QKVCOLS + NH * HD + kh * HD;
    const float* vnew = g_qkv + b * QKVCOLS + (NH + NKV) * HD + kh * HD;
    const int* btab = block_offsets + b * NBLK;
    const float scale = 0.08838834764831845f;

    const int ir = (t >> 5);       // staging: thread covers rows i*4 + ir
    const int c4 = (t & 31);       // and cols c4*4

    // ================= Phase A: scores =================
    float sc[NT];

    // stage K tile 0 into buffer 0 (stride KS, ULL stores)
    {
        const int base = base0;
        const int phys = btab[base >> 6];
        const float* kb = k_cache + ((size_t)(phys * PBLOCK + (base & 63)) * NKV + kh) * HD;
        #pragma unroll
        for (int i = 0; i < 8; i++) {
            const int r = i * 4 + ir;
            const float4 v4 = (base + r == last)
                ? *(const float4*)(knew + c4 * 4)
                : *(const float4*)(kb + (size_t)r * (NKV * HD) + c4 * 4);
            unsigned long long* dst = (unsigned long long*)(kv_s[0] + r * KS + c4 * 4);
            dst[0] = pk2(v4.x, v4.y); dst[1] = pk2(v4.z, v4.w);
        }
    }
    __syncthreads();

    for (int tl = 0; tl < NT; tl++) {
        float4 pf[8];
        if (tl < NT - 1) {   // prefetch next K tile to regs
            const int base = base0 + (tl + 1) * TK;
            const int phys = btab[base >> 6];
            const float* kb = k_cache + ((size_t)(phys * PBLOCK + (base & 63)) * NKV + kh) * HD;
            #pragma unroll
            for (int i = 0; i < 8; i++) {
                const int r = i * 4 + ir;
                pf[i] = (base + r == last)
                    ? *(const float4*)(knew + c4 * 4)
                    : *(const float4*)(kb + (size_t)r * (NKV * HD) + c4 * 4);
            }
        }
        // 4-way split dot: thread (g, key=lane)
        const unsigned long long* kp = (const unsigned long long*)(kv_s[tl & 1] + lane * KS);
        const unsigned long long* qp = (const unsigned long long*)(q_s + (g << 7));
        unsigned long long d0 = 0ULL, d1 = 0ULL, d2 = 0ULL, d3 = 0ULL;
        #pragma unroll
        for (int jj = 0; jj < 16; jj++) {
            ffma2(d0, kp[4 * jj],     qp[4 * jj]);
            ffma2(d1, kp[4 * jj + 1], qp[4 * jj + 1]);
            ffma2(d2, kp[4 * jj + 2], qp[4 * jj + 2]);
            ffma2(d3, kp[4 * jj + 3], qp[4 * jj + 3]);
        }
        float a0, a1, b0, b1, e0, e1, f0, f1;
        upk2(d0, a0, a1); upk2(d1, b0, b1); upk2(d2, e0, e1); upk2(d3, f0, f1);
        float scv = ((a0 + a1) + (b0 + b1) + ((e0 + e1) + (f0 + f1))) * scale;
        if (base0 + tl * TK + lane >= kv_len) scv = -1e30f;
        sc[tl] = scv;

        if (tl < NT - 1) {   // commit prefetched tile to other buffer
            #pragma unroll
            for (int i = 0; i < 8; i++) {
                const int r = i * 4 + ir;
                unsigned long long* dst =
                    (unsigned long long*)(kv_s[(tl + 1) & 1] + r * KS + c4 * 4);
                dst[0] = pk2(pf[i].x, pf[i].y); dst[1] = pk2(pf[i].z, pf[i].w);
            }
        }
        __syncthreads();
    }

    // ================= Phase B: one softmax pass =================
    float m = sc[0];
    #pragma unroll
    for (int tl = 1; tl < NT; tl++) m = fmaxf(m, sc[tl]);
    #pragma unroll
    for (int o = 16; o; o >>= 1) m = fmaxf(m, __shfl_xor_sync(0xffffffffu, m, o));
    float l = 0.f;
    #pragma unroll
    for (int tl = 0; tl < NT; tl++) {
        const float p = __expf(sc[tl] - m);
        l += p;
        p_s[(g << 9) + tl * TK + lane] = p;
    }
    #pragma unroll
    for (int o = 16; o; o >>= 1) l += __shfl_xor_sync(0xffffffffu, l, o);
    __syncwarp();

    // ================= Phase C: weighted V =================
    float4 acc[4];
    #pragma unroll
    for (int j = 0; j < 4; j++) acc[j] = make_float4(0.f, 0.f, 0.f, 0.f);

    // stage V tile 0 into buffer 0 (stride VS, float4 stores)
    {
        const int base = base0;
        const int phys = btab[base >> 6];
        const float* vb = v_cache + ((size_t)(phys * PBLOCK + (base & 63)) * NKV + kh) * HD;
        #pragma unroll
        for (int i = 0; i < 8; i++) {
            const int r = i * 4 + ir;
            const float4 v4 = (base + r == last)
                ? *(const float4*)(vnew + c4 * 4)
                : *(const float4*)(vb + (size_t)r * (NKV * HD) + c4 * 4);
            *(float4*)(kv_s[0] + r * VS + c4 * 4) = v4;
        }
    }
    __syncthreads();

    for (int tl = 0; tl < NT; tl++) {
        float4 pf[8];
        if (tl < NT - 1) {
            const int base = base0 + (tl + 1) * TK;
            const int phys = btab[base >> 6];
            const float* vb = v_cache + ((size_t)(phys * PBLOCK + (base & 63)) * NKV + kh) * HD;
            #pragma unroll
            for (int i = 0; i < 8; i++) {
                const int r = i * 4 + ir;
                pf[i] = (base + r == last)
                    ? *(const float4*)(vnew + c4 * 4)
                    : *(const float4*)(vb + (size_t)r * (NKV * HD) + c4 * 4);
            }
        }
        const float* vs = kv_s[tl & 1];
        const float* pp = p_s + (g << 9) + tl * TK;
        #pragma unroll
        for (int kk = 0; kk < TK; kk++) {
            const float pkv = pp[kk];
            const float4 v4 = *(const float4*)(vs + kk * VS + (lane << 2));
            float4& A = acc[kk & 3];
            A.x += pkv * v4.x; A.y += pkv * v4.y;
            A.z += pkv * v4.z; A.w += pkv * v4.w;
        }
        if (tl < NT - 1) {
            #pragma unroll
            for (int i = 0; i < 8; i++) {
                const int r = i * 4 + ir;
                *(float4*)(kv_s[(tl + 1) & 1] + r * VS + c4 * 4) = pf[i];
            }
            __syncthreads();
        }
    }

    float4 r;
    r.x = (acc[0].x + acc[1].x) + (acc[2].x + acc[3].x);
    r.y = (acc[0].y + acc[1].y) + (acc[2].y + acc[3].y);
    r.z = (acc[0].z + acc[1].z) + (acc[2].z + acc[3].z);
    r.w = (acc[0].w + acc[1].w) + (acc[2].w + acc[3].w);
    *(float4*)(P + (lane << 2)) = r;
    if (lane == 0) { P[128] = m; P[129] = l; }
}

// ---------------- combine splits ----------------
// grid (NKV, BATCH), block (128,4): thread = (dim d, group g)
__global__ __launch_bounds__(512) void combine_kernel()
{
    const int kh = blockIdx.x, b = blockIdx.y;
    const int d = threadIdx.x, g = threadIdx.y;
    const float* Pb = g_part + ((size_t)(b * NKV + kh)) * NS * SSTR + g * GSTR;
    float M = -1e30f;
    #pragma unroll
    for (int s = 0; s < NS; s++) M = fmaxf(M, Pb[s * SSTR + 128]);
    float Ls = 0.f, o = 0.f;
    #pragma unroll
    for (int s = 0; s < NS; s++) {
        const float w = __expf(Pb[s * SSTR + 128] - M);
        Ls += w * Pb[s * SSTR + 129];
        o  += w * Pb[s * SSTR + d];
    }
    g_attn[b * DMODEL + (kh * GQA + g) * HD + d] = o / Ls;
}

// ---------------- reduce output split-K partials ----------------
__global__ __launch_bounds__(256) void reduce_out_kernel(float* __restrict__ out)
{
    const int i = blockIdx.x * 256 + threadIdx.x;
    if (i < BATCH * DMODEL) {
        float v = 0.f;
        #pragma unroll
        for (int s = 0; s < KSPLITS; s++)
            v += g_out_part[(size_t)s * BATCH * DMODEL + i];
        out[i] = v;
    }
}

// ---------------- launcher ----------------
extern "C" void kernel_launch(void* const* d_in, const int* in_sizes, int n_in,
                              void* d_out, int out_size)
{
    const float* hidden  = (const float*)d_in[0];
    const float* wqkv    = (const float*)d_in[1];
    const float* wo      = (const float*)d_in[2];
    const float* k_cache = (const float*)d_in[3];
    const float* v_cache = (const float*)d_in[4];
    const int* pos_ids   = (const int*)d_in[5];
    const int* blk_off   = (const int*)d_in[6];
    const int* kv_lens   = (const int*)d_in[7];
    float* out = (float*)d_out;

    gemm_splitk<QKVCOLS, 0><<<dim3(QKVCOLS / 512, KSPLITS), 128>>>(hidden, wqkv);
    rope_reduce_kernel<<<dim3(6, BATCH), 256>>>(pos_ids);
    attn_split_kernel<<<dim3(NS, NKV, BATCH), 128>>>(k_cache, v_cache, blk_off, kv_lens);
    combine_kernel<<<dim3(NKV, BATCH), dim3(128, 4)>>>();
    gemm_splitk<DMODEL, 1><<<dim3(DMODEL / 512, KSPLITS), 128>>>(hidden, wo);
    reduce_out_kernel<<<(BATCH * DMODEL + 255) / 256, 256>>>(out);
}

// round 12
// speedup vs baseline: 1.4766x; 1.1101x over previous
#include <cuda_runtime.h>
#include <cuda_bf16.h>
#include <math.h>

// ---------------- problem constants ----------------
#define BATCH   32
#define DMODEL  4096
#define NH      32
#define NKV     8
#define GQA     4
#define HD      128
#define PBLOCK  64
#define NBLK    64
#define LMAX    (NBLK * PBLOCK)          // 4096
#define QKVCOLS ((NH + 2 * NKV) * HD)    // 6144

// attention tiling
#define ASPLIT  512
#define NS      (LMAX / ASPLIT)          // 8
#define TK      32
#define NT      (ASPLIT / TK)            // 16 tiles per split
#define KS      130                      // K smem stride (floats): odd ULL stride -> conflict-free LDS.64
#define VS      132                      // V smem stride (floats): odd 16B stride -> conflict-free LDS.128
#define GSTR    132
#define SSTR    (GQA * GSTR)             // 528

// split-K GEMM
#define KSPLITS 32
#define KRANGE  (DMODEL / KSPLITS)       // 128

// ---------------- device scratch ----------------
__device__ float g_qkv_part[KSPLITS * BATCH * QKVCOLS];
__device__ __align__(16) float g_qkv[BATCH * QKVCOLS];
__device__ __align__(16) float g_part[BATCH * NKV * NS * SSTR];
__device__ __align__(16) float g_attn[BATCH * NH * HD];
__device__ float g_out_part[KSPLITS * BATCH * DMODEL];

// ---------------- f32x2 helpers ----------------
__device__ __forceinline__ unsigned long long pk2(float x, float y) {
    unsigned long long r;
    asm("mov.b64 %0, {%1, %2};" : "=l"(r) : "f"(x), "f"(y));
    return r;
}
__device__ __forceinline__ void upk2(unsigned long long v, float& x, float& y) {
    asm("mov.b64 {%0, %1}, %2;" : "=f"(x), "=f"(y) : "l"(v));
}
__device__ __forceinline__ void ffma2(unsigned long long& d,
                                      unsigned long long a,
                                      unsigned long long b) {
    asm("fma.rn.f32x2 %0, %1, %2, %0;" : "+l"(d) : "l"(a), "l"(b));
}

// ---------------- split-K GEMM ----------------
// MODE 0: C=g_qkv_part, A=Ain (hidden).  MODE 1: C=g_out_part, A=g_attn.
template <int N, int MODE>
__global__ __launch_bounds__(128) void gemm_splitk(
    const float* __restrict__ Ain, const float* __restrict__ W)
{
    const float* __restrict__ A = (MODE == 0) ? Ain : (const float*)g_attn;
    float* __restrict__ Cpart   = (MODE == 0) ? g_qkv_part : g_out_part;

    __shared__ __align__(16) float a_s[KRANGE][34];

    const int t  = threadIdx.x;
    const int k0 = blockIdx.y * KRANGE;
    const int c0 = blockIdx.x * 512 + t * 4;

    #pragma unroll 8
    for (int bb = 0; bb < 32; bb++)
        a_s[t][bb] = A[bb * DMODEL + k0 + t];
    __syncthreads();

    unsigned long long acc2[16][4];
    #pragma unroll
    for (int p = 0; p < 16; p++)
        #pragma unroll
        for (int j = 0; j < 4; j++)
            acc2[p][j] = 0ULL;

    const float* Wp = W + (size_t)k0 * N + c0;

    #pragma unroll 4
    for (int kk = 0; kk < KRANGE; kk++) {
        const float4 w4 = *(const float4*)(Wp + (size_t)kk * N);
        const unsigned long long wx = pk2(w4.x, w4.x);
        const unsigned long long wy = pk2(w4.y, w4.y);
        const unsigned long long wz = pk2(w4.z, w4.z);
        const unsigned long long ww = pk2(w4.w, w4.w);
        const unsigned long long* ap = (const unsigned long long*)(&a_s[kk][0]);
        #pragma unroll
        for (int p = 0; p < 16; p++) {
            const unsigned long long h2 = ap[p];
            ffma2(acc2[p][0], h2, wx);
            ffma2(acc2[p][1], h2, wy);
            ffma2(acc2[p][2], h2, wz);
            ffma2(acc2[p][3], h2, ww);
        }
    }

    float* Cb = Cpart + (size_t)blockIdx.y * 32 * N + c0;
    #pragma unroll
    for (int p = 0; p < 16; p++) {
        float4 r0, r1;
        upk2(acc2[p][0], r0.x, r1.x);
        upk2(acc2[p][1], r0.y, r1.y);
        upk2(acc2[p][2], r0.z, r1.z);
        upk2(acc2[p][3], r0.w, r1.w);
        *(float4*)(Cb + (size_t)(2 * p) * N)     = r0;
        *(float4*)(Cb + (size_t)(2 * p + 1) * N) = r1;
    }
}

// ---------------- reduce qkv partials + RoPE ----------------
__global__ __launch_bounds__(256) void rope_reduce_kernel(
    const int* __restrict__ position_ids)
{
    __shared__ float buf[1024];
    __shared__ float cosv[64], sinv[64];
    const int chunk = blockIdx.x;
    const int b = blockIdx.y;
    const int t = threadIdx.x;
    const int c0 = chunk * 1024;

    #pragma unroll
    for (int c = t; c < 1024; c += 256) {
        float v = 0.f;
        #pragma unroll
        for (int s = 0; s < KSPLITS; s++)
            v += g_qkv_part[(size_t)s * BATCH * QKVCOLS + b * QKVCOLS + c0 + c];
        buf[c] = v;
    }
    if (t < 64) {
        const double inv = exp(-(2.0 * t / 128.0) * log(1.0e6));
        const double ang = (double)position_ids[b] * inv;
        cosv[t] = (float)cos(ang);
        sinv[t] = (float)sin(ang);
    }
    __syncthreads();

    float* out = g_qkv + b * QKVCOLS + c0;
    if (c0 < 5120) {
        #pragma unroll
        for (int idx = t; idx < 512; idx += 256) {
            const int head = idx >> 6, i = idx & 63;
            const int lb = head * 128;
            const float x1 = buf[lb + i], x2 = buf[lb + i + 64];
            const float c = cosv[i], s = sinv[i];
            out[lb + i]      = x1 * c - x2 * s;
            out[lb + i + 64] = x2 * c + x1 * s;
        }
    } else {
        #pragma unroll
        for (int c = t; c < 1024; c += 256)
            out[c] = buf[c];
    }
}

// ---------------- flash-decoding split attention ----------------
// grid (NS, NKV, BATCH), 128 threads.
// Phase A: warp = dim-quarter (all 4 heads).  Phase C: warp = key-octet (all 4 heads).
__global__ __launch_bounds__(128) void attn_split_kernel(
    const float* __restrict__ k_cache, const float* __restrict__ v_cache,
    const int* __restrict__ block_offsets, const int* __restrict__ kv_seqlens)
{
    __shared__ __align__(16) float q_s[GQA * HD];          // 2 KB
    __shared__ __align__(16) float kv_s[2][TK * VS];       // 33 KB (K staged @stride 130 inside)
    __shared__ __align__(16) float p_s[ASPLIT * GQA];      // 8 KB: [key][4 heads]
    __shared__ float pp_s[2][GQA * GQA * TK];              // 4 KB: [buf][w][h][key]

    const int s    = blockIdx.x;
    const int kh   = blockIdx.y;
    const int b    = blockIdx.z;
    const int t    = threadIdx.x;
    const int g    = t >> 5;      // warp id
    const int lane = t & 31;

    const int kv_len = kv_seqlens[b];
    const int last   = kv_len - 1;
    const int base0  = s * ASPLIT;

    float* P = g_part + (((size_t)(b * NKV + kh)) * NS + s) * SSTR + g * GSTR;

    if (base0 >= kv_len) {
        const float4 z = {0.f, 0.f, 0.f, 0.f};
        *(float4*)(P + (lane << 2)) = z;
        if (lane == 0) { P[128] = -1e30f; P[129] = 0.f; }
        return;
    }

    #pragma unroll
    for (int i = 0; i < GQA; i++)
        q_s[i * HD + t] = g_qkv[b * QKVCOLS + (kh * GQA + i) * HD + t];

    const float* knew = g_qkv + b * QKVCOLS + NH * HD + kh * HD;
    const float* vnew = g_qkv + b * QKVCOLS + (NH + NKV) * HD + kh * HD;
    const int* btab = block_offsets + b * NBLK;
    const float scale = 0.08838834764831845f;

    const int ir = g;              // staging: thread covers rows i*4 + ir
    const int c4 = lane;           // and cols c4*4

    // ================= Phase A: scores (dim-split across warps) =================
    float sc[NT];

    // stage K tile 0 into buffer 0 (stride KS, ULL stores)
    {
        const int base = base0;
        const int phys = btab[base >> 6];
        const float* kb = k_cache + ((size_t)(phys * PBLOCK + (base & 63)) * NKV + kh) * HD;
        #pragma unroll
        for (int i = 0; i < 8; i++) {
            const int r = i * 4 + ir;
            const float4 v4 = (base + r == last)
                ? *(const float4*)(knew + c4 * 4)
                : *(const float4*)(kb + (size_t)r * (NKV * HD) + c4 * 4);
            unsigned long long* dst = (unsigned long long*)(kv_s[0] + r * KS + c4 * 4);
            dst[0] = pk2(v4.x, v4.y); dst[1] = pk2(v4.z, v4.w);
        }
    }
    __syncthreads();

    for (int tl = 0; tl < NT; tl++) {
        float4 pf[8];
        if (tl < NT - 1) {   // prefetch next K tile to regs
            const int base = base0 + (tl + 1) * TK;
            const int phys = btab[base >> 6];
            const float* kb = k_cache + ((size_t)(phys * PBLOCK + (base & 63)) * NKV + kh) * HD;
            #pragma unroll
            for (int i = 0; i < 8; i++) {
                const int r = i * 4 + ir;
                pf[i] = (base + r == last)
                    ? *(const float4*)(knew + c4 * 4)
                    : *(const float4*)(kb + (size_t)r * (NKV * HD) + c4 * 4);
            }
        }

        // dim-split dot: warp g covers dims [32g,32g+32) for ALL 4 heads; lane = key.
        {
            const unsigned long long* kp =
                (const unsigned long long*)(kv_s[tl & 1] + lane * KS + (g << 5));
            const unsigned long long* q0 = (const unsigned long long*)(q_s + 0 * HD + (g << 5));
            const unsigned long long* q1 = (const unsigned long long*)(q_s + 1 * HD + (g << 5));
            const unsigned long long* q2 = (const unsigned long long*)(q_s + 2 * HD + (g << 5));
            const unsigned long long* q3 = (const unsigned long long*)(q_s + 3 * HD + (g << 5));
            unsigned long long d0 = 0ULL, d1 = 0ULL, d2 = 0ULL, d3 = 0ULL;
            #pragma unroll
            for (int j = 0; j < 16; j++) {
                const unsigned long long kc = kp[j];
                ffma2(d0, kc, q0[j]);
                ffma2(d1, kc, q1[j]);
                ffma2(d2, kc, q2[j]);
                ffma2(d3, kc, q3[j]);
            }
            float x, y;
            float* pw = pp_s[tl & 1] + (g << 7) + lane;   // [w=g][h][key=lane]
            upk2(d0, x, y); pw[0]  = x + y;
            upk2(d1, x, y); pw[32] = x + y;
            upk2(d2, x, y); pw[64] = x + y;
            upk2(d3, x, y); pw[96] = x + y;
        }

        if (tl < NT - 1) {   // commit prefetched tile to other buffer
            #pragma unroll
            for (int i = 0; i < 8; i++) {
                const int r = i * 4 + ir;
                unsigned long long* dst =
                    (unsigned long long*)(kv_s[(tl + 1) & 1] + r * KS + c4 * 4);
                dst[0] = pk2(pf[i].x, pf[i].y); dst[1] = pk2(pf[i].z, pf[i].w);
            }
        }
        __syncthreads();

        // reduce tile tl partials across warps: thread (h=g, key=lane)
        {
            const float* pr = pp_s[tl & 1] + (g << 5) + lane;  // [w][h=g][lane]
            float v = (pr[0] + pr[128]) + (pr[256] + pr[384]);
            v *= scale;
            if (base0 + tl * TK + lane >= kv_len) v = -1e30f;
            sc[tl] = v;
        }
    }

    // ================= Phase B: one softmax pass (warp = head g) =================
    float m = sc[0];
    #pragma unroll
    for (int tl = 1; tl < NT; tl++) m = fmaxf(m, sc[tl]);
    #pragma unroll
    for (int o = 16; o; o >>= 1) m = fmaxf(m, __shfl_xor_sync(0xffffffffu, m, o));
    float l = 0.f;
    #pragma unroll
    for (int tl = 0; tl < NT; tl++) {
        const float p = __expf(sc[tl] - m);
        l += p;
        p_s[((tl * TK + lane) << 2) + g] = p;   // packed [key][head]
    }
    #pragma unroll
    for (int o = 16; o; o >>= 1) l += __shfl_xor_sync(0xffffffffu, l, o);
    if (lane == 0) { P[128] = m; P[129] = l; }

    // stage V tile 0 into buffer 0 (stride VS, float4 stores); K15 lives in kv_s[1]
    {
        const int base = base0;
        const int phys = btab[base >> 6];
        const float* vb = v_cache + ((size_t)(phys * PBLOCK + (base & 63)) * NKV + kh) * HD;
        #pragma unroll
        for (int i = 0; i < 8; i++) {
            const int r = i * 4 + ir;
            const float4 v4 = (base + r == last)
                ? *(const float4*)(vnew + c4 * 4)
                : *(const float4*)(vb + (size_t)r * (NKV * HD) + c4 * 4);
            *(float4*)(kv_s[0] + r * VS + c4 * 4) = v4;
        }
    }
    __syncthreads();   // p_s + V0 visible

    // ================= Phase C: weighted V (key-split across warps) =================
    // warp g covers keys [8g, 8g+8) per tile for ALL 4 heads; lane = dim-chunk (4 floats).
    unsigned long long acc[GQA][2];
    #pragma unroll
    for (int h = 0; h < GQA; h++) { acc[h][0] = 0ULL; acc[h][1] = 0ULL; }

    for (int tl = 0; tl < NT; tl++) {
        float4 pf[8];
        if (tl < NT - 1) {
            const int base = base0 + (tl + 1) * TK;
            const int phys = btab[base >> 6];
            const float* vb = v_cache + ((size_t)(phys * PBLOCK + (base & 63)) * NKV + kh) * HD;
            #pragma unroll
            for (int i = 0; i < 8; i++) {
                const int r = i * 4 + ir;
                pf[i] = (base + r == last)
                    ? *(const float4*)(vnew + c4 * 4)
                    : *(const float4*)(vb + (size_t)r * (NKV * HD) + c4 * 4);
            }
        }

        const float* vs = kv_s[tl & 1];
        const float* pp = p_s + ((tl * TK + (g << 3)) << 2);
        #pragma unroll
        for (int kk = 0; kk < 8; kk++) {
            const float4 p4 = *(const float4*)(pp + (kk << 2));           // broadcast
            const ulonglong2 v2 =
                *(const ulonglong2*)(vs + ((g << 3) + kk) * VS + (lane << 2));
            const unsigned long long p0 = pk2(p4.x, p4.x);
            const unsigned long long p1 = pk2(p4.y, p4.y);
            const unsigned long long p2 = pk2(p4.z, p4.z);
            const unsigned long long p3 = pk2(p4.w, p4.w);
            ffma2(acc[0][0], p0, v2.x); ffma2(acc[0][1], p0, v2.y);
            ffma2(acc[1][0], p1, v2.x); ffma2(acc[1][1], p1, v2.y);
            ffma2(acc[2][0], p2, v2.x); ffma2(acc[2][1], p2, v2.y);
            ffma2(acc[3][0], p3, v2.x); ffma2(acc[3][1], p3, v2.y);
        }

        if (tl < NT - 1) {
            #pragma unroll
            for (int i = 0; i < 8; i++) {
                const int r = i * 4 + ir;
                *(float4*)(kv_s[(tl + 1) & 1] + r * VS + c4 * 4) = pf[i];
            }
            __syncthreads();
        }
    }

    // cross-warp reduce of key-split outputs: red[w][h][128 dims] in kv_s[0] area
    {
        float* red = kv_s[0];   // last V tile (15) was in kv_s[1]; kv_s[0] free
        #pragma unroll
        for (int h = 0; h < GQA; h++) {
            float4 r4;
            upk2(acc[h][0], r4.x, r4.y);
            upk2(acc[h][1], r4.z, r4.w);
            *(float4*)(red + (g << 9) + (h << 7) + (lane << 2)) = r4;
        }
    }
    __syncthreads();

    {
        const float* red = kv_s[0];
        const float4 a0 = *(const float4*)(red + 0    + (g << 7) + (lane << 2));
        const float4 a1 = *(const float4*)(red + 512  + (g << 7) + (lane << 2));
        const float4 a2 = *(const float4*)(red + 1024 + (g << 7) + (lane << 2));
        const float4 a3 = *(const float4*)(red + 1536 + (g << 7) + (lane << 2));
        float4 r;
        r.x = (a0.x + a1.x) + (a2.x + a3.x);
        r.y = (a0.y + a1.y) + (a2.y + a3.y);
        r.z = (a0.z + a1.z) + (a2.z + a3.z);
        r.w = (a0.w + a1.w) + (a2.w + a3.w);
        *(float4*)(P + (lane << 2)) = r;   // P already offset by head g
    }
}

// ---------------- combine splits ----------------
__global__ __launch_bounds__(512) void combine_kernel()
{
    const int kh = blockIdx.x, b = blockIdx.y;
    const int d = threadIdx.x, g = threadIdx.y;
    const float* Pb = g_part + ((size_t)(b * NKV + kh)) * NS * SSTR + g * GSTR;
    float M = -1e30f;
    #pragma unroll
    for (int s = 0; s < NS; s++) M = fmaxf(M, Pb[s * SSTR + 128]);
    float Ls = 0.f, o = 0.f;
    #pragma unroll
    for (int s = 0; s < NS; s++) {
        const float w = __expf(Pb[s * SSTR + 128] - M);
        Ls += w * Pb[s * SSTR + 129];
        o  += w * Pb[s * SSTR + d];
    }
    g_attn[b * DMODEL + (kh * GQA + g) * HD + d] = o / Ls;
}

// ---------------- reduce output split-K partials ----------------
__global__ __launch_bounds__(256) void reduce_out_kernel(float* __restrict__ out)
{
    const int i = blockIdx.x * 256 + threadIdx.x;
    if (i < BATCH * DMODEL) {
        float v = 0.f;
        #pragma unroll
        for (int s = 0; s < KSPLITS; s++)
            v += g_out_part[(size_t)s * BATCH * DMODEL + i];
        out[i] = v;
    }
}

// ---------------- launcher ----------------
extern "C" void kernel_launch(void* const* d_in, const int* in_sizes, int n_in,
                              void* d_out, int out_size)
{
    const float* hidden  = (const float*)d_in[0];
    const float* wqkv    = (const float*)d_in[1];
    const float* wo      = (const float*)d_in[2];
    const float* k_cache = (const float*)d_in[3];
    const float* v_cache = (const float*)d_in[4];
    const int* pos_ids   = (const int*)d_in[5];
    const int* blk_off   = (const int*)d_in[6];
    const int* kv_lens   = (const int*)d_in[7];
    float* out = (float*)d_out;

    gemm_splitk<QKVCOLS, 0><<<dim3(QKVCOLS / 512, KSPLITS), 128>>>(hidden, wqkv);
    rope_reduce_kernel<<<dim3(6, BATCH), 256>>>(pos_ids);
    attn_split_kernel<<<dim3(NS, NKV, BATCH), 128>>>(k_cache, v_cache, blk_off, kv_lens);
    combine_kernel<<<dim3(NKV, BATCH), dim3(128, 4)>>>();
    gemm_splitk<DMODEL, 1><<<dim3(DMODEL / 512, KSPLITS), 128>>>(hidden, wo);
    reduce_out_kernel<<<(BATCH * DMODEL + 255) / 256, 256>>>(out);
}